// round 7
// baseline (speedup 1.0000x reference)
#include <cuda_runtime.h>
#include <cuda_bf16.h>

// y = Re(FFT_2048(x_row)); out = LayerNorm(y)*gamma + beta.  16384 rows, C=2048.
// Four-step FFT: 1024 = 32x32, one warp/row, 32 complex elems/thread.
// Register FFT-32 (radix-2 DIF, const twiddles), one padded smem transpose,
// conjugate unpack via PAIRED SHUFFLES (no smem round trip), LN warp reduce.

#define C 2048
#define H 1024
#define RPC 4
#define PITCH 33
#define PI_F 3.14159265358979323846f
#define RS2 0.70710678118654752f

__device__ __forceinline__ float2 cmul(float2 a, float2 b) {
    return make_float2(fmaf(a.x, b.x, -a.y * b.y), fmaf(a.x, b.y, a.y * b.x));
}
__device__ __forceinline__ float2 csq(float2 a) {
    return make_float2(fmaf(a.x, a.x, -a.y * a.y), 2.0f * a.x * a.y);
}
__device__ __forceinline__ float2 cadd(float2 a, float2 b) { return make_float2(a.x + b.x, a.y + b.y); }
__device__ __forceinline__ float2 csub(float2 a, float2 b) { return make_float2(a.x - b.x, a.y - b.y); }

__device__ __forceinline__ int br5(int x) {
    return ((x & 1) << 4) | ((x & 2) << 2) | (x & 4) | ((x & 8) >> 2) | ((x & 16) >> 4);
}

__device__ __forceinline__ float2 w32c(int e) {
    const float CO[16] = {1.f, 0.98078528f, 0.92387953f, 0.83146961f, 0.70710678f,
                          0.55557023f, 0.38268343f, 0.19509032f, 0.f, -0.19509032f,
                          -0.38268343f, -0.55557023f, -0.70710678f, -0.83146961f,
                          -0.92387953f, -0.98078528f};
    const float SI[16] = {0.f, 0.19509032f, 0.38268343f, 0.55557023f, 0.70710678f,
                          0.83146961f, 0.92387953f, 0.98078528f, 1.f, 0.98078528f,
                          0.92387953f, 0.83146961f, 0.70710678f, 0.55557023f,
                          0.38268343f, 0.19509032f};
    return make_float2(CO[e], -SI[e]);
}

template <int M>
__device__ __forceinline__ void fft32_stage(float2 v[32]) {
#pragma unroll
    for (int b = 0; b < 32; b += 2 * M)
#pragma unroll
        for (int i = 0; i < M; i++) {
            float2 u = v[b + i], t = v[b + i + M];
            v[b + i] = cadd(u, t);
            float2 d = csub(u, t);
            const int e = i * (16 / M);
            if (e == 0)      v[b + i + M] = d;
            else if (e == 8) v[b + i + M] = make_float2(d.y, -d.x);  // *(-i)
            else             v[b + i + M] = cmul(d, w32c(e));
        }
}
__device__ __forceinline__ void fft32(float2 v[32]) {
    fft32_stage<16>(v); fft32_stage<8>(v); fft32_stage<4>(v);
    fft32_stage<2>(v);  fft32_stage<1>(v);
}

__global__ void __launch_bounds__(128, 5)
fourier_ln_kernel(const float* __restrict__ x,
                  const float* __restrict__ gamma,
                  const float* __restrict__ beta,
                  float* __restrict__ out) {
    __shared__ __align__(16) float2 xch[RPC][32 * PITCH];

    const int lane = threadIdx.x & 31;
    const int warp = threadIdx.x >> 5;
    const size_t row = (size_t)blockIdx.x * RPC + warp;
    const float2* xr = reinterpret_cast<const float2*>(x) + row * H;

    // step 1: coalesced load, FFT-32 over b
    float2 g[32];
#pragma unroll
    for (int b = 0; b < 32; b++) g[b] = xr[lane + 32 * b];
    fft32(g);                    // g[br5(c)] = G_a[c]

    // step 2: G_a[c] *= W_1024^{a*c}; squaring ladder (depth ~5)
    {
        float sb, cb;
        __sincosf(-(float)lane * (PI_F / 512.0f), &sb, &cb);
        float2 p1 = make_float2(cb, sb);
        float2 p2 = csq(p1), p3 = cmul(p1, p2), p4 = csq(p2);
        float2 p5 = cmul(p4, p1), p6 = csq(p3), p7 = cmul(p4, p3);
        float2 w8 = csq(p4), w16 = csq(w8), w24 = cmul(w16, w8);
        g[br5(8)]  = cmul(g[br5(8)],  w8);
        g[br5(16)] = cmul(g[br5(16)], w16);
        g[br5(24)] = cmul(g[br5(24)], w24);
        float2 pc[7] = {p1, p2, p3, p4, p5, p6, p7};
#pragma unroll
        for (int c = 1; c < 8; c++) {
            float2 w = pc[c - 1];
            g[br5(c)]      = cmul(g[br5(c)], w);
            g[br5(c + 8)]  = cmul(g[br5(c + 8)],  cmul(w, w8));
            g[br5(c + 16)] = cmul(g[br5(c + 16)], cmul(w, w16));
            g[br5(c + 24)] = cmul(g[br5(c + 24)], cmul(w, w24));
        }
    }

    // step 3: 32x32 transpose through padded smem
    float2* sh = &xch[warp][0];
#pragma unroll
    for (int c = 0; c < 32; c++) sh[lane * PITCH + c] = g[br5(c)];
    __syncwarp();
#pragma unroll
    for (int a = 0; a < 32; a++) g[a] = sh[a * PITCH + lane];

    // step 4: FFT-32 over a.  g[br5(d)] = Z[lane + 32*d]
    fft32(g);
    const float re1024 = g[0].x - g[0].y;      // lane 0: ReX[1024]

    // unpack ReX[k] via paired shuffles.  Pair (d, 31-d), d=0..15.
    // Partner of k=lane+32d lives at lane L=(32-lane)&31, register br5(31-d)
    // (the pair's other member) -> exchange both members with lane L.
    // re_lo overwrites g[br5(d)].x immediately; re_hi write is delayed one
    // iteration (lane 0 reads g[br5(32-d)] at iter d before that write).
    float s = 0.f, ss = 0.f;
    {
        const int L = (32 - lane) & 31;
        const float UC = 0.99518472667f, US = 0.09801714033f;  // e^{-i pi/32}
        float su, cu;
        __sincosf(-(float)lane * (PI_F / 1024.0f), &su, &cu);
        float2 A  = make_float2(cu, su);                 // e^{-i pi lane/1024}
        float2 wl = A;                                   // w(k= lane+32d), d=0
        float2 wh = cmul(A, make_float2(-UC, -US));      // w(k= lane+32*31)
        float pend = 0.f;
#pragma unroll
        for (int d = 0; d < 16; d++) {
            float2 z1 = g[br5(d)];
            float2 z2 = g[br5(31 - d)];
            float px1 = __shfl_sync(0xFFFFFFFFu, z2.x, L);
            float py1 = __shfl_sync(0xFFFFFFFFu, z2.y, L);
            float px2 = __shfl_sync(0xFFFFFFFFu, z1.x, L);
            float py2 = __shfl_sync(0xFFFFFFFFu, z1.y, L);
            if (lane == 0) {                 // self-partners at lane 0
                float2 o1 = g[br5((32 - d) & 31)];
                float2 o2 = g[br5(d + 1)];
                px1 = o1.x; py1 = o1.y;
                px2 = o2.x; py2 = o2.y;
            }
            if (d > 0) g[br5(32 - d)].x = pend;          // delayed re_hi(d-1)
            float re1 = 0.5f * ((z1.x + px1) +
                        fmaf(wl.x, z1.y + py1, wl.y * (z1.x - px1)));
            float re2 = 0.5f * ((z2.x + px2) +
                        fmaf(wh.x, z2.y + py2, wh.y * (z2.x - px2)));
            g[br5(d)].x = re1;
            pend = re2;
            s  += 2.0f * (re1 + re2);
            ss  = fmaf(2.0f * re1, re1, fmaf(2.0f * re2, re2, ss));
            wl = cmul(wl, make_float2(UC, -US));
            wh = cmul(wh, make_float2(UC,  US));
        }
        g[br5(16)].x = pend;                             // re_hi(15)
    }
    if (lane == 0) {                 // k=0, k=1024 count once each
        float re0 = g[br5(0)].x;
        s  += re1024 - re0;
        ss += fmaf(re1024, re1024, -re0 * re0);
    }
#pragma unroll
    for (int o = 16; o > 0; o >>= 1) {
        s  += __shfl_xor_sync(0xFFFFFFFFu, s, o);
        ss += __shfl_xor_sync(0xFFFFFFFFu, ss, o);
    }
    const float mu = s * (1.0f / C);
    const float rstd = rsqrtf(ss * (1.0f / C) - mu * mu + 1e-5f);

    // normalize + affine + mirrored stores
    float* orow = out + row * C;
#pragma unroll
    for (int d = 0; d < 32; d++) {
        int k = lane + 32 * d;
        float vv = (g[br5(d)].x - mu) * rstd;
        orow[k] = fmaf(vv, __ldg(&gamma[k]), __ldg(&beta[k]));
        if (k != 0) {
            int km = C - k;
            orow[km] = fmaf(vv, __ldg(&gamma[km]), __ldg(&beta[km]));
        }
    }
    if (lane == 0) {
        float vv = (re1024 - mu) * rstd;
        orow[H] = fmaf(vv, __ldg(&gamma[H]), __ldg(&beta[H]));
    }
}

extern "C" void kernel_launch(void* const* d_in, const int* in_sizes, int n_in,
                              void* d_out, int out_size) {
    const float* x     = (const float*)d_in[0];
    const float* gamma = (const float*)d_in[1];
    const float* beta  = (const float*)d_in[2];
    float* out = (float*)d_out;
    int rows = in_sizes[0] / C;            // 16384
    fourier_ln_kernel<<<rows / RPC, 32 * RPC>>>(x, gamma, beta, out);
}